// round 4
// baseline (speedup 1.0000x reference)
#include <cuda_runtime.h>
#include <cuda_fp16.h>

// Problem constants (fixed by reference setup_inputs)
#define N_MAX   (384*384)     // 147456 pixels
#define A_FEAT  32            // features per pixel
#define K_NBR   48            // neighbors per pixel
#define EPSV    1e-9f

// Scratch: row-major fp16 feature table UU[N][32] (64B rows, 128B-aligned base).
__device__ __align__(128) __half g_UUh[N_MAX * A_FEAT];

// ---------------------------------------------------------------------------
// Kernel 1: transpose + compress input1 [32, N] fp32 -> g_UUh [N, 32] fp16
// ---------------------------------------------------------------------------
__global__ void transpose_kernel(const float* __restrict__ in, int N) {
    __shared__ float tile[32][33];
    const int n0 = blockIdx.x * 32;
    const int tx = threadIdx.x;      // 0..31
    const int ty = threadIdx.y;      // 0..7
#pragma unroll
    for (int i = 0; i < 32; i += 8) {
        tile[ty + i][tx] = in[(size_t)(ty + i) * N + n0 + tx];
    }
    __syncthreads();
#pragma unroll
    for (int i = 0; i < 32; i += 8) {
        g_UUh[(size_t)(n0 + ty + i) * A_FEAT + tx] = __float2half(tile[tx][ty + i]);
    }
}

// One-line predicated gather: only lanes of group `G` execute the load.
// asm volatile keeps ptxas from merging the four complementary loads back
// into a single 4-line LDG (which pays the 2.07 cyc/wf within-LDG replay).
#define PRED_GATHER(G)                                                        \
    asm volatile("{\n\t"                                                      \
                 ".reg .pred p;\n\t"                                          \
                 "setp.eq.s32 p, %2, " #G ";\n\t"                             \
                 "@p ld.global.nc.v2.u32 {%0,%1}, [%3];\n\t"                  \
                 "}"                                                          \
                 : "+r"(lo), "+r"(hi)                                         \
                 : "r"(wgrp), "l"(gaddr))

// ---------------------------------------------------------------------------
// Kernel 2: per-pixel distance + softmax.
// 8 lanes per pixel: lane gl owns 4 fp16 features (8B) of the 64B row.
// Gather: 4 predicated one-line LDG.64s per warp-step (one per pixel group).
// ---------------------------------------------------------------------------
__global__ void __launch_bounds__(256) dist_softmax_kernel(
        const int* __restrict__ idx,       // [N, 48] int32
        float* __restrict__ out, int N) {
    const int tid = blockIdx.x * blockDim.x + threadIdx.x;
    const int j    = tid >> 3;              // pixel
    const int gl   = tid & 7;               // lane within 8-lane group
    const int wgrp = (threadIdx.x >> 3) & 3; // pixel-group within warp
    if (j >= N) return;

    // global-space base address of the fp16 table
    unsigned long long gbase;
    {
        const __half* p = g_UUh;
        asm("cvta.to.global.u64 %0, %1;" : "=l"(gbase) : "l"(p));
    }
    const unsigned long long goff = (unsigned long long)(gl << 3); // lane byte offset in row

    // own feature chunk: 4 halves -> fp32
    const __half2* __restrict__ UUh2 = reinterpret_cast<const __half2*>(g_UUh);
    const int base_own = j * 16 + gl * 2;
    const float2 ua = __half22float2(UUh2[base_own + 0]);
    const float2 ub = __half22float2(UUh2[base_own + 1]);

    // preload the 6 neighbor indices this lane is responsible for (k = t*8+gl)
    int myidx[6];
    const int* __restrict__ idx_row = idx + (size_t)j * K_NBR;
#pragma unroll
    for (int t = 0; t < 6; t++) {
        int v = idx_row[t * 8 + gl];
        myidx[t] = min(max(v, 0), N - 1);   // defensive clamp
    }

    float D[6];
#pragma unroll
    for (int t = 0; t < 6; t++) {
#pragma unroll
        for (int s = 0; s < 8; s++) {
            const int nk = __shfl_sync(0xffffffffu, myidx[t], s, 8);
            const unsigned long long gaddr =
                gbase + ((unsigned long long)(unsigned)nk << 6) + goff;
            unsigned lo = 0u, hi = 0u;
            PRED_GATHER(0);
            PRED_GATHER(1);
            PRED_GATHER(2);
            PRED_GATHER(3);
            const float2 va = __half22float2(*reinterpret_cast<const __half2*>(&lo));
            const float2 vb = __half22float2(*reinterpret_cast<const __half2*>(&hi));
            const float d0 = ua.x - va.x;
            const float d1 = ua.y - va.y;
            const float d2 = ub.x - vb.x;
            const float d3 = ub.y - vb.y;
            float acc = d0 * d0;
            acc = fmaf(d1, d1, acc);
            acc = fmaf(d2, d2, acc);
            acc = fmaf(d3, d3, acc);
            // reduce across the 8 lanes of the group
            acc += __shfl_xor_sync(0xffffffffu, acc, 1, 8);
            acc += __shfl_xor_sync(0xffffffffu, acc, 2, 8);
            acc += __shfl_xor_sync(0xffffffffu, acc, 4, 8);
            if (s == gl) D[t] = acc;   // lane gl keeps neighbor k = t*8+gl
        }
    }

    // D_k = -sqrt(mean + eps)
#pragma unroll
    for (int t = 0; t < 6; t++) {
        D[t] = -sqrtf(fmaf(D[t], 1.0f / 32.0f, EPSV));
    }

    // softmax over 48 (6 local values x 8 lanes)
    float m = D[0];
#pragma unroll
    for (int t = 1; t < 6; t++) m = fmaxf(m, D[t]);
    m = fmaxf(m, __shfl_xor_sync(0xffffffffu, m, 1, 8));
    m = fmaxf(m, __shfl_xor_sync(0xffffffffu, m, 2, 8));
    m = fmaxf(m, __shfl_xor_sync(0xffffffffu, m, 4, 8));

    float e[6];
    float ssum = 0.0f;
#pragma unroll
    for (int t = 0; t < 6; t++) {
        e[t] = __expf(D[t] - m);
        ssum += e[t];
    }
    ssum += __shfl_xor_sync(0xffffffffu, ssum, 1, 8);
    ssum += __shfl_xor_sync(0xffffffffu, ssum, 2, 8);
    ssum += __shfl_xor_sync(0xffffffffu, ssum, 4, 8);

    const float inv = 1.0f / ssum;
    float* __restrict__ orow = out + (size_t)j * K_NBR;
#pragma unroll
    for (int t = 0; t < 6; t++) {
        orow[t * 8 + gl] = e[t] * inv;
    }
}

// ---------------------------------------------------------------------------
extern "C" void kernel_launch(void* const* d_in, const int* in_sizes, int n_in,
                              void* d_out, int out_size) {
    const float* input1 = (const float*)d_in[0];   // [32, N] fp32
    const int*   input2 = (const int*)d_in[1];     // [N, 48] int32 (JAX x64 off)
    float*       out    = (float*)d_out;           // [N, 48] fp32

    const int N = in_sizes[0] / A_FEAT;   // 147456

    // 1) transpose + fp16 compress
    {
        dim3 blk(32, 8);
        dim3 grd(N / 32);
        transpose_kernel<<<grd, blk>>>(input1, N);
    }
    // 2) distances + softmax: 8 threads per pixel
    {
        const int threads = 256;
        const long long total = (long long)N * 8;
        const int blocks = (int)((total + threads - 1) / threads);
        dist_softmax_kernel<<<blocks, threads>>>(input2, out, N);
    }
}

// round 5
// speedup vs baseline: 1.2645x; 1.2645x over previous
#include <cuda_runtime.h>
#include <cuda_fp16.h>

#define N_MAX   (384*384)     // 147456 pixels
#define A_FEAT  32            // features per pixel
#define K_NBR   48            // neighbors per pixel
#define EPSV    1e-9f

// Row-major fp16 feature table UU[N][32] (64B rows, 128B-aligned base).
__device__ __align__(128) __half g_UUh[N_MAX * A_FEAT];

// ---------------------------------------------------------------------------
// Kernel 1: transpose + compress input1 [32, N] fp32 -> g_UUh [N, 32] fp16
// (vectorized half2 stores)
// ---------------------------------------------------------------------------
__global__ void transpose_kernel(const float* __restrict__ in, int N) {
    __shared__ float tile[32][33];
    const int n0 = blockIdx.x * 32;
    const int tx = threadIdx.x;      // 0..31
    const int ty = threadIdx.y;      // 0..7
#pragma unroll
    for (int i = 0; i < 32; i += 8) {
        tile[ty + i][tx] = in[(size_t)(ty + i) * N + n0 + tx];
    }
    __syncthreads();
    // write phase: 512 half2 per block, 2 per thread
    __half2* __restrict__ out2 = reinterpret_cast<__half2*>(g_UUh);
    const int id = ty * 32 + tx;          // 0..255
    const int c  = id & 15;               // half2 column 0..15
    const int r0 = id >> 4;               // 0..15
#pragma unroll
    for (int rr = 0; rr < 2; rr++) {
        const int r = r0 + rr * 16;
        const float a = tile[2 * c][r];
        const float b = tile[2 * c + 1][r];
        out2[(size_t)(n0 + r) * 16 + c] = __floats2half2_rn(a, b);
    }
}

// ---------------------------------------------------------------------------
// Kernel 2: per-pixel distance + softmax.
// 8 lanes per pixel (4 pixels/warp). Gather per step: TWO independent
// LDG.64s, each touching exactly 2 cache lines (half-warp duplicated),
// selected per-lane with one hoisted predicate.
// ---------------------------------------------------------------------------
__global__ void __launch_bounds__(256) dist_softmax_kernel(
        const int* __restrict__ idx,       // [N, 48] int32
        float* __restrict__ out, int N) {
    const int tid = blockIdx.x * blockDim.x + threadIdx.x;
    const int j  = tid >> 3;            // pixel
    const int wl = threadIdx.x & 31;    // lane within warp
    const int gl = wl & 7;              // lane within 8-lane group
    if (j >= N) return;

    // global pointer base (char units) + per-lane byte offset within row
    const char* gUU = reinterpret_cast<const char*>(g_UUh);
    const char* baseLane = gUU + (gl << 3);

    // pair-bit: which of the two groups in this lane's half the LDG targets
    const int pairbit = (wl >> 3) & 1;          // 0 or 1
    const bool upperHalf = (wl & 16) != 0;      // lanes 16..31 use LDG B

    // own feature chunk: 4 halves as 2x half2
    __half2 uh0, uh1;
    {
        const uint2 uraw = *reinterpret_cast<const uint2*>(
            gUU + ((size_t)j << 6) + (gl << 3));
        uh0 = *reinterpret_cast<const __half2*>(&uraw.x);
        uh1 = *reinterpret_cast<const __half2*>(&uraw.y);
    }

    // preload 6 neighbor indices (lane gl of each group holds k = t*8+gl)
    int myidx[6];
    const int* __restrict__ idx_row = idx + (size_t)j * K_NBR;
#pragma unroll
    for (int t = 0; t < 6; t++) {
        int v = idx_row[t * 8 + gl];
        myidx[t] = min(max(v, 0), N - 1);   // defensive clamp
    }

    const int srcBaseA = (pairbit << 3);        // group 0/1's lane s
    const int srcBaseB = 16 + (pairbit << 3);   // group 2/3's lane s

    float D[6];
#pragma unroll
    for (int t = 0; t < 6; t++) {
#pragma unroll
        for (int s = 0; s < 8; s++) {
            // one computed-source broadcast per LDG
            const int nkA = __shfl_sync(0xffffffffu, myidx[t], srcBaseA + s, 32);
            const int nkB = __shfl_sync(0xffffffffu, myidx[t], srcBaseB + s, 32);
            // two independent 2-line gathers (64B rows, dup across half-warps)
            const uint2 rA = *reinterpret_cast<const uint2*>(
                baseLane + ((size_t)(unsigned)nkA << 6));
            const uint2 rB = *reinterpret_cast<const uint2*>(
                baseLane + ((size_t)(unsigned)nkB << 6));
            const unsigned lo = upperHalf ? rB.x : rA.x;
            const unsigned hi = upperHalf ? rB.y : rA.y;

            const __half2 vh0 = *reinterpret_cast<const __half2*>(&lo);
            const __half2 vh1 = *reinterpret_cast<const __half2*>(&hi);
            const __half2 d0 = __hsub2(uh0, vh0);
            const __half2 d1 = __hsub2(uh1, vh1);
            const __half2 q  = __hfma2(d1, d1, __hmul2(d0, d0));
            float acc = __low2float(q) + __high2float(q);

            // reduce across the 8 lanes of the group
            acc += __shfl_xor_sync(0xffffffffu, acc, 1, 8);
            acc += __shfl_xor_sync(0xffffffffu, acc, 2, 8);
            acc += __shfl_xor_sync(0xffffffffu, acc, 4, 8);
            D[t] = (s == gl) ? acc : D[t];
        }
    }

    // D_k = -sqrt(mean + eps)
#pragma unroll
    for (int t = 0; t < 6; t++) {
        D[t] = -sqrtf(fmaf(D[t], 1.0f / 32.0f, EPSV));
    }

    // softmax over 48 (6 local values x 8 lanes)
    float m = D[0];
#pragma unroll
    for (int t = 1; t < 6; t++) m = fmaxf(m, D[t]);
    m = fmaxf(m, __shfl_xor_sync(0xffffffffu, m, 1, 8));
    m = fmaxf(m, __shfl_xor_sync(0xffffffffu, m, 2, 8));
    m = fmaxf(m, __shfl_xor_sync(0xffffffffu, m, 4, 8));

    float e[6];
    float ssum = 0.0f;
#pragma unroll
    for (int t = 0; t < 6; t++) {
        e[t] = __expf(D[t] - m);
        ssum += e[t];
    }
    ssum += __shfl_xor_sync(0xffffffffu, ssum, 1, 8);
    ssum += __shfl_xor_sync(0xffffffffu, ssum, 2, 8);
    ssum += __shfl_xor_sync(0xffffffffu, ssum, 4, 8);

    const float inv = 1.0f / ssum;
    float* __restrict__ orow = out + (size_t)j * K_NBR;
#pragma unroll
    for (int t = 0; t < 6; t++) {
        orow[t * 8 + gl] = e[t] * inv;
    }
}

// ---------------------------------------------------------------------------
extern "C" void kernel_launch(void* const* d_in, const int* in_sizes, int n_in,
                              void* d_out, int out_size) {
    const float* input1 = (const float*)d_in[0];   // [32, N] fp32
    const int*   input2 = (const int*)d_in[1];     // [N, 48] int32 (JAX x64 off)
    float*       out    = (float*)d_out;           // [N, 48] fp32

    const int N = in_sizes[0] / A_FEAT;   // 147456

    {
        dim3 blk(32, 8);
        dim3 grd(N / 32);
        transpose_kernel<<<grd, blk>>>(input1, N);
    }
    {
        const int threads = 256;
        const long long total = (long long)N * 8;
        const int blocks = (int)((total + threads - 1) / threads);
        dist_softmax_kernel<<<blocks, threads>>>(input2, out, N);
    }
}

// round 7
// speedup vs baseline: 2.2675x; 1.7932x over previous
#include <cuda_runtime.h>
#include <cuda_fp16.h>

#define N_MAX   (384*384)     // 147456 pixels
#define A_FEAT  32            // features per pixel
#define K_NBR   48            // neighbors per pixel
#define EPSV    1e-9f

// Row-major fp16 feature table UU[N][32] (64B rows, 128B-aligned base).
__device__ __align__(128) __half g_UUh[N_MAX * A_FEAT];

// ---------------------------------------------------------------------------
// Kernel 1: transpose + compress input1 [32, N] fp32 -> g_UUh [N, 32] fp16
// ---------------------------------------------------------------------------
__global__ void transpose_kernel(const float* __restrict__ in, int N) {
    __shared__ float tile[32][33];
    const int n0 = blockIdx.x * 32;
    const int tx = threadIdx.x;      // 0..31
    const int ty = threadIdx.y;      // 0..7
#pragma unroll
    for (int i = 0; i < 32; i += 8) {
        tile[ty + i][tx] = in[(size_t)(ty + i) * N + n0 + tx];
    }
    __syncthreads();
    __half2* __restrict__ out2 = reinterpret_cast<__half2*>(g_UUh);
    const int id = ty * 32 + tx;          // 0..255
    const int c  = id & 15;               // half2 column 0..15
    const int r0 = id >> 4;               // 0..15
#pragma unroll
    for (int rr = 0; rr < 2; rr++) {
        const int r = r0 + rr * 16;
        out2[(size_t)(n0 + r) * 16 + c] =
            __floats2half2_rn(tile[2 * c][r], tile[2 * c + 1][r]);
    }
}

// ---------------------------------------------------------------------------
// Kernel 2: per-pixel distance + softmax. R3 gather (one 4-line LDG.64 per
// step, 4 pixels/warp), batched MLP=8, fp16x2 diff math, and a 7-shuffle
// multi-value butterfly that reduces all 8 neighbor partials at once.
// ---------------------------------------------------------------------------
__global__ void __launch_bounds__(256) dist_softmax_kernel(
        const int* __restrict__ idx,       // [N, 48] int32
        float* __restrict__ out, int N) {
    const int tid = blockIdx.x * blockDim.x + threadIdx.x;
    const int j  = tid >> 3;             // pixel
    const int gl = threadIdx.x & 7;      // lane within 8-lane group
    if (j >= N) return;

    const char* __restrict__ gUU = reinterpret_cast<const char*>(g_UUh);
    const char* __restrict__ gUUlane = gUU + (gl << 3);  // lane's 8B slot

    // own feature chunk: 4 halves as 2x half2
    __half2 uh0, uh1;
    {
        const uint2 uraw = *reinterpret_cast<const uint2*>(
            gUU + ((size_t)(unsigned)j << 6) + (gl << 3));
        uh0 = *reinterpret_cast<const __half2*>(&uraw.x);
        uh1 = *reinterpret_cast<const __half2*>(&uraw.y);
    }

    // preload 6 neighbor byte-offsets (lane gl holds k = t*8+gl)
    int off[6];
    const int* __restrict__ idx_row = idx + (size_t)j * K_NBR;
#pragma unroll
    for (int t = 0; t < 6; t++) {
        int v = idx_row[t * 8 + gl];
        off[t] = min(max(v, 0), N - 1) << 6;   // row byte offset
    }

    const bool b0 = (gl & 1) != 0;
    const bool b1 = (gl & 2) != 0;
    const bool b2 = (gl & 4) != 0;

    float D[6];
#pragma unroll
    for (int t = 0; t < 6; t++) {
        // batch: issue all 8 gathers (each a 4-line LDG.64, MLP=8)
        uint2 r[8];
#pragma unroll
        for (int s = 0; s < 8; s++) {
            const int o = __shfl_sync(0xffffffffu, off[t], s, 8);
            r[s] = *reinterpret_cast<const uint2*>(gUUlane + (size_t)(unsigned)o);
        }
        // per-neighbor partial (this lane's 4 features), fp16x2
        float acc[8];
#pragma unroll
        for (int s = 0; s < 8; s++) {
            const __half2 vh0 = *reinterpret_cast<const __half2*>(&r[s].x);
            const __half2 vh1 = *reinterpret_cast<const __half2*>(&r[s].y);
            const __half2 d0 = __hsub2(uh0, vh0);
            const __half2 d1 = __hsub2(uh1, vh1);
            const __half2 q  = __hfma2(d1, d1, __hmul2(d0, d0));
            acc[s] = __low2float(q) + __high2float(q);
        }
        // multi-value butterfly: 7 shfl total, lane gl ends with s = gl
        float t4[4];
#pragma unroll
        for (int k = 0; k < 4; k++) {
            const float keep = b0 ? acc[2 * k + 1] : acc[2 * k];
            const float send = b0 ? acc[2 * k]     : acc[2 * k + 1];
            t4[k] = keep + __shfl_xor_sync(0xffffffffu, send, 1, 8);
        }
        float t2[2];
#pragma unroll
        for (int m = 0; m < 2; m++) {
            const float keep = b1 ? t4[2 * m + 1] : t4[2 * m];
            const float send = b1 ? t4[2 * m]     : t4[2 * m + 1];
            t2[m] = keep + __shfl_xor_sync(0xffffffffu, send, 2, 8);
        }
        {
            const float keep = b2 ? t2[1] : t2[0];
            const float send = b2 ? t2[0] : t2[1];
            D[t] = keep + __shfl_xor_sync(0xffffffffu, send, 4, 8);
        }
    }

    // D_k = -sqrt(mean + eps)
#pragma unroll
    for (int t = 0; t < 6; t++) {
        D[t] = -sqrtf(fmaf(D[t], 1.0f / 32.0f, EPSV));
    }

    // softmax over 48 (6 local values x 8 lanes)
    float m = D[0];
#pragma unroll
    for (int t = 1; t < 6; t++) m = fmaxf(m, D[t]);
    m = fmaxf(m, __shfl_xor_sync(0xffffffffu, m, 1, 8));
    m = fmaxf(m, __shfl_xor_sync(0xffffffffu, m, 2, 8));
    m = fmaxf(m, __shfl_xor_sync(0xffffffffu, m, 4, 8));

    float e[6];
    float ssum = 0.0f;
#pragma unroll
    for (int t = 0; t < 6; t++) {
        e[t] = __expf(D[t] - m);
        ssum += e[t];
    }
    ssum += __shfl_xor_sync(0xffffffffu, ssum, 1, 8);
    ssum += __shfl_xor_sync(0xffffffffu, ssum, 2, 8);
    ssum += __shfl_xor_sync(0xffffffffu, ssum, 4, 8);

    const float inv = 1.0f / ssum;
    float* __restrict__ orow = out + (size_t)j * K_NBR;
#pragma unroll
    for (int t = 0; t < 6; t++) {
        orow[t * 8 + gl] = e[t] * inv;
    }
}

// ---------------------------------------------------------------------------
extern "C" void kernel_launch(void* const* d_in, const int* in_sizes, int n_in,
                              void* d_out, int out_size) {
    const float* input1 = (const float*)d_in[0];   // [32, N] fp32
    const int*   input2 = (const int*)d_in[1];     // [N, 48] int32 (JAX x64 off)
    float*       out    = (float*)d_out;           // [N, 48] fp32

    const int N = in_sizes[0] / A_FEAT;   // 147456

    {
        dim3 blk(32, 8);
        dim3 grd(N / 32);
        transpose_kernel<<<grd, blk>>>(input1, N);
    }
    {
        const int threads = 256;
        const long long total = (long long)N * 8;
        const int blocks = (int)((total + threads - 1) / threads);
        dist_softmax_kernel<<<blocks, threads>>>(input2, out, N);
    }
}

// round 8
// speedup vs baseline: 2.3826x; 1.0507x over previous
#include <cuda_runtime.h>
#include <cuda_fp16.h>

#define N_MAX   (384*384)     // 147456 pixels
#define A_FEAT  32            // features per pixel
#define K_NBR   48            // neighbors per pixel
#define EPSV    1e-9f

// Row-major fp16 feature table UU[N][32] (64B rows, 128B-aligned base).
__device__ __align__(128) __half g_UUh[N_MAX * A_FEAT];

// ---------------------------------------------------------------------------
// Kernel 1: transpose + compress input1 [32, N] fp32 -> g_UUh [N, 32] fp16
// ---------------------------------------------------------------------------
__global__ void transpose_kernel(const float* __restrict__ in, int N) {
    __shared__ float tile[32][33];
    const int n0 = blockIdx.x * 32;
    const int tx = threadIdx.x;      // 0..31
    const int ty = threadIdx.y;      // 0..7
#pragma unroll
    for (int i = 0; i < 32; i += 8) {
        tile[ty + i][tx] = in[(size_t)(ty + i) * N + n0 + tx];
    }
    __syncthreads();
    __half2* __restrict__ out2 = reinterpret_cast<__half2*>(g_UUh);
    const int id = ty * 32 + tx;          // 0..255
    const int c  = id & 15;               // half2 column 0..15
    const int r0 = id >> 4;               // 0..15
#pragma unroll
    for (int rr = 0; rr < 2; rr++) {
        const int r = r0 + rr * 16;
        out2[(size_t)(n0 + r) * 16 + c] =
            __floats2half2_rn(tile[2 * c][r], tile[2 * c + 1][r]);
    }
}

// ---------------------------------------------------------------------------
// Kernel 2: 4 lanes per pixel (8 pixels/warp). Lane owns 16B (8 features).
// Gather: one LDG.128 per step covering 8 rows (1 line each). 12 t-groups of
// 4 neighbors, MLP=4 batched loads, fp16x2 dual-chain math, 3-shfl
// multi-value butterfly (width 4). Output staged via padded smem -> STG.128.
// ---------------------------------------------------------------------------
__global__ void __launch_bounds__(256) dist_softmax_kernel(
        const int* __restrict__ idx,       // [N, 48] int32
        float* __restrict__ out, int N) {
    const int gtid   = blockIdx.x * blockDim.x + threadIdx.x;
    const int warpId = gtid >> 5;
    const int lane   = threadIdx.x & 31;
    const int p      = lane >> 2;        // pixel within warp 0..7
    const int gl     = lane & 3;         // lane within 4-lane group
    const int j      = warpId * 8 + p;   // pixel
    const int wIdx   = threadIdx.x >> 5; // warp within block
    if (j >= N) return;

    __shared__ float stage[8][8][52];    // [warp][pixel][48 padded to 52]

    const char* __restrict__ gUU = reinterpret_cast<const char*>(g_UUh);
    const char* __restrict__ gUUlane = gUU + (gl << 4);   // lane's 16B slot

    // own 8 features as 4x half2
    __half2 uh0, uh1, uh2, uh3;
    {
        const uint4 uraw = *reinterpret_cast<const uint4*>(
            gUU + ((size_t)(unsigned)j << 6) + (gl << 4));
        uh0 = *reinterpret_cast<const __half2*>(&uraw.x);
        uh1 = *reinterpret_cast<const __half2*>(&uraw.y);
        uh2 = *reinterpret_cast<const __half2*>(&uraw.z);
        uh3 = *reinterpret_cast<const __half2*>(&uraw.w);
    }

    // idx preload: lane gl owns neighbors gl*12 .. gl*12+11 (3x LDG.128)
    int off[12];
    {
        const int4* __restrict__ idx4 = reinterpret_cast<const int4*>(
            idx + (size_t)j * K_NBR + gl * 12);
#pragma unroll
        for (int q = 0; q < 3; q++) {
            const int4 v = idx4[q];
            off[q * 4 + 0] = min(max(v.x, 0), N - 1) << 6;
            off[q * 4 + 1] = min(max(v.y, 0), N - 1) << 6;
            off[q * 4 + 2] = min(max(v.z, 0), N - 1) << 6;
            off[q * 4 + 3] = min(max(v.w, 0), N - 1) << 6;
        }
    }

    const bool b0 = (gl & 1) != 0;
    const bool b1 = (gl & 2) != 0;

    float D[12];
#pragma unroll
    for (int t = 0; t < 12; t++) {
        const int srcLane = t / 3;          // lane (within group) holding this t-group
        const int e0      = (t % 3) * 4;    // its component base
        // batch 4 gathers (each LDG.128 covers 8 rows, MLP=4)
        uint4 r[4];
#pragma unroll
        for (int s = 0; s < 4; s++) {
            const int o = __shfl_sync(0xffffffffu, off[e0 + s], srcLane, 4);
            r[s] = *reinterpret_cast<const uint4*>(gUUlane + (size_t)(unsigned)o);
        }
        // per-neighbor partial (this lane's 8 features), two depth-2 fp16 chains
        float acc[4];
#pragma unroll
        for (int s = 0; s < 4; s++) {
            const __half2 vh0 = *reinterpret_cast<const __half2*>(&r[s].x);
            const __half2 vh1 = *reinterpret_cast<const __half2*>(&r[s].y);
            const __half2 vh2 = *reinterpret_cast<const __half2*>(&r[s].z);
            const __half2 vh3 = *reinterpret_cast<const __half2*>(&r[s].w);
            const __half2 d0 = __hsub2(uh0, vh0);
            const __half2 d1 = __hsub2(uh1, vh1);
            const __half2 d2 = __hsub2(uh2, vh2);
            const __half2 d3 = __hsub2(uh3, vh3);
            const __half2 qa = __hfma2(d1, d1, __hmul2(d0, d0));
            const __half2 qb = __hfma2(d3, d3, __hmul2(d2, d2));
            acc[s] = (__low2float(qa) + __high2float(qa))
                   + (__low2float(qb) + __high2float(qb));
        }
        // multi-value butterfly over 4 partials: 3 shfl, lane gl keeps s=gl
        const float u0 = b0 ? acc[1] : acc[0];
        const float s0 = b0 ? acc[0] : acc[1];
        const float u1 = b0 ? acc[3] : acc[2];
        const float s1 = b0 ? acc[2] : acc[3];
        const float m0 = u0 + __shfl_xor_sync(0xffffffffu, s0, 1, 4);
        const float m1 = u1 + __shfl_xor_sync(0xffffffffu, s1, 1, 4);
        const float uu = b1 ? m1 : m0;
        const float ss = b1 ? m0 : m1;
        D[t] = uu + __shfl_xor_sync(0xffffffffu, ss, 2, 4);
    }

    // D_k = -sqrt(mean + eps)
#pragma unroll
    for (int t = 0; t < 12; t++) {
        D[t] = -sqrtf(fmaf(D[t], 1.0f / 32.0f, EPSV));
    }

    // softmax over 48 (12 local values x 4 lanes)
    float m = D[0];
#pragma unroll
    for (int t = 1; t < 12; t++) m = fmaxf(m, D[t]);
    m = fmaxf(m, __shfl_xor_sync(0xffffffffu, m, 1, 4));
    m = fmaxf(m, __shfl_xor_sync(0xffffffffu, m, 2, 4));

    float ssum = 0.0f;
#pragma unroll
    for (int t = 0; t < 12; t++) {
        D[t] = __expf(D[t] - m);   // reuse D as exp values
        ssum += D[t];
    }
    ssum += __shfl_xor_sync(0xffffffffu, ssum, 1, 4);
    ssum += __shfl_xor_sync(0xffffffffu, ssum, 2, 4);
    const float inv = 1.0f / ssum;

    // stage into padded smem (conflict-free: 52-float rows), then coalesced out
#pragma unroll
    for (int t = 0; t < 12; t++) {
        stage[wIdx][p][t * 4 + gl] = D[t] * inv;
    }
    __syncwarp();

    // per-warp contiguous 1536B output: lane writes floats [lane*12, lane*12+12)
    {
        float* __restrict__ owarp = out + (size_t)warpId * 8 * K_NBR;
        const int pr = lane >> 2;                 // source pixel row
        const int kb = 12 * (lane & 3);           // base column
#pragma unroll
        for (int i = 0; i < 3; i++) {
            const float4 v = *reinterpret_cast<const float4*>(
                &stage[wIdx][pr][kb + 4 * i]);
            *reinterpret_cast<float4*>(owarp + lane * 12 + 4 * i) = v;
        }
    }
}

// ---------------------------------------------------------------------------
extern "C" void kernel_launch(void* const* d_in, const int* in_sizes, int n_in,
                              void* d_out, int out_size) {
    const float* input1 = (const float*)d_in[0];   // [32, N] fp32
    const int*   input2 = (const int*)d_in[1];     // [N, 48] int32 (JAX x64 off)
    float*       out    = (float*)d_out;           // [N, 48] fp32

    const int N = in_sizes[0] / A_FEAT;   // 147456

    {
        dim3 blk(32, 8);
        dim3 grd(N / 32);
        transpose_kernel<<<grd, blk>>>(input1, N);
    }
    {
        const int threads = 256;
        const long long total = (long long)N * 4;   // 4 lanes per pixel
        const int blocks = (int)((total + threads - 1) / threads);
        dist_softmax_kernel<<<blocks, threads>>>(input2, out, N);
    }
}

// round 9
// speedup vs baseline: 2.4462x; 1.0267x over previous
#include <cuda_runtime.h>
#include <cuda_fp16.h>

#define N_MAX   (384*384)     // 147456 pixels
#define A_FEAT  32            // features per pixel
#define K_NBR   48            // neighbors per pixel
#define EPSV    1e-9f

// Row-major fp16 feature table UU[N][32] (64B rows, 128B-aligned base).
__device__ __align__(128) __half g_UUh[N_MAX * A_FEAT];

// ---------------------------------------------------------------------------
// Kernel 1: transpose + compress input1 [32, N] fp32 -> g_UUh [N, 32] fp16
// ---------------------------------------------------------------------------
__global__ void transpose_kernel(const float* __restrict__ in, int N) {
    __shared__ float tile[32][33];
    const int n0 = blockIdx.x * 32;
    const int tx = threadIdx.x;      // 0..31
    const int ty = threadIdx.y;      // 0..7
#pragma unroll
    for (int i = 0; i < 32; i += 8) {
        tile[ty + i][tx] = in[(size_t)(ty + i) * N + n0 + tx];
    }
    __syncthreads();
    __half2* __restrict__ out2 = reinterpret_cast<__half2*>(g_UUh);
    const int id = ty * 32 + tx;          // 0..255
    const int c  = id & 15;               // half2 column 0..15
    const int r0 = id >> 4;               // 0..15
#pragma unroll
    for (int rr = 0; rr < 2; rr++) {
        const int r = r0 + rr * 16;
        out2[(size_t)(n0 + r) * 16 + c] =
            __floats2half2_rn(tile[2 * c][r], tile[2 * c + 1][r]);
    }
}

__device__ __forceinline__ int clampShift(int v, int N) {
    return min(max(v, 0), N - 1) << 6;
}

// ---------------------------------------------------------------------------
// Kernel 2: 4 lanes per pixel (8 pixels/warp). Lane owns 16B (8 features).
// Gather: one LDG.128 per step covering 4 rows (1 line each), MLP=4.
// Schedule: t-group t -> srcLane = t%4, int4 #q = t/4 (double-buffered idx).
// Softmax without max-subtraction (D<=0 always): exp computed in-loop,
// e-values staged in padded smem, normalized on the coalesced write-out.
// ---------------------------------------------------------------------------
__global__ void __launch_bounds__(256, 5) dist_softmax_kernel(
        const int* __restrict__ idx,       // [N, 48] int32
        float* __restrict__ out, int N) {
    const int gtid   = blockIdx.x * blockDim.x + threadIdx.x;
    const int warpId = gtid >> 5;
    const int lane   = threadIdx.x & 31;
    const int p      = lane >> 2;        // pixel within warp 0..7
    const int gl     = lane & 3;         // lane within 4-lane group
    const int j      = warpId * 8 + p;   // pixel
    const int wIdx   = threadIdx.x >> 5; // warp within block
    if (j >= N) return;

    __shared__ float stage[8][8][52];    // [warp][pixel][48 padded to 52]
    __shared__ float invs[8][8];         // [warp][pixel] 1/sum

    const char* __restrict__ gUU = reinterpret_cast<const char*>(g_UUh);
    const char* __restrict__ gUUlane = gUU + (gl << 4);   // lane's 16B slot

    // own 8 features as 4x half2
    __half2 uh0, uh1, uh2, uh3;
    {
        const uint4 uraw = *reinterpret_cast<const uint4*>(
            gUU + ((size_t)(unsigned)j << 6) + (gl << 4));
        uh0 = *reinterpret_cast<const __half2*>(&uraw.x);
        uh1 = *reinterpret_cast<const __half2*>(&uraw.y);
        uh2 = *reinterpret_cast<const __half2*>(&uraw.z);
        uh3 = *reinterpret_cast<const __half2*>(&uraw.w);
    }

    const bool b0 = (gl & 1) != 0;
    const bool b1 = (gl & 2) != 0;

    // idx int4 #q for lane gl sits at idx4[4*q + gl] (neighbors 16q+4gl+{0..3})
    const int4* __restrict__ idx4 =
        reinterpret_cast<const int4*>(idx + (size_t)j * K_NBR);

    int4 cur = idx4[gl];
    cur.x = clampShift(cur.x, N); cur.y = clampShift(cur.y, N);
    cur.z = clampShift(cur.z, N); cur.w = clampShift(cur.w, N);

    float ssum = 0.0f;
#pragma unroll
    for (int q = 0; q < 3; q++) {
        int4 nxt;
        if (q < 2) nxt = idx4[4 * (q + 1) + gl];   // prefetch raw
#pragma unroll
        for (int st = 0; st < 4; st++) {
            const int t = q * 4 + st;
            // broadcast srcLane's 4 byte-offsets, batch 4 LDG.128 (MLP=4)
            const int o0 = __shfl_sync(0xffffffffu, cur.x, st, 4);
            const int o1 = __shfl_sync(0xffffffffu, cur.y, st, 4);
            const int o2 = __shfl_sync(0xffffffffu, cur.z, st, 4);
            const int o3 = __shfl_sync(0xffffffffu, cur.w, st, 4);
            uint4 r0 = *reinterpret_cast<const uint4*>(gUUlane + (size_t)(unsigned)o0);
            uint4 r1 = *reinterpret_cast<const uint4*>(gUUlane + (size_t)(unsigned)o1);
            uint4 r2 = *reinterpret_cast<const uint4*>(gUUlane + (size_t)(unsigned)o2);
            uint4 r3 = *reinterpret_cast<const uint4*>(gUUlane + (size_t)(unsigned)o3);

            float acc[4];
            {
                const uint4* rr[4] = { &r0, &r1, &r2, &r3 };
#pragma unroll
                for (int s = 0; s < 4; s++) {
                    const __half2 vh0 = *reinterpret_cast<const __half2*>(&rr[s]->x);
                    const __half2 vh1 = *reinterpret_cast<const __half2*>(&rr[s]->y);
                    const __half2 vh2 = *reinterpret_cast<const __half2*>(&rr[s]->z);
                    const __half2 vh3 = *reinterpret_cast<const __half2*>(&rr[s]->w);
                    const __half2 d0 = __hsub2(uh0, vh0);
                    const __half2 d1 = __hsub2(uh1, vh1);
                    const __half2 d2 = __hsub2(uh2, vh2);
                    const __half2 d3 = __hsub2(uh3, vh3);
                    const __half2 qa = __hfma2(d1, d1, __hmul2(d0, d0));
                    const __half2 qb = __hfma2(d3, d3, __hmul2(d2, d2));
                    acc[s] = (__low2float(qa) + __high2float(qa))
                           + (__low2float(qb) + __high2float(qb));
                }
            }
            // 3-shfl multi-value butterfly (width 4): lane gl keeps s = gl
            const float u0 = b0 ? acc[1] : acc[0];
            const float s0 = b0 ? acc[0] : acc[1];
            const float u1 = b0 ? acc[3] : acc[2];
            const float s1 = b0 ? acc[2] : acc[3];
            const float m0 = u0 + __shfl_xor_sync(0xffffffffu, s0, 1, 4);
            const float m1 = u1 + __shfl_xor_sync(0xffffffffu, s1, 1, 4);
            const float uu = b1 ? m1 : m0;
            const float sv = b1 ? m0 : m1;
            const float Dt = uu + __shfl_xor_sync(0xffffffffu, sv, 2, 4);

            // e = exp(-sqrt(mean+eps))  (no max-sub needed: arg in (-10, 0])
            const float e = __expf(-sqrtf(fmaf(Dt, 1.0f / 32.0f, EPSV)));
            ssum += e;
            stage[wIdx][p][t * 4 + gl] = e;   // conflict-free (52-float rows)
        }
        if (q < 2) {
            nxt.x = clampShift(nxt.x, N); nxt.y = clampShift(nxt.y, N);
            nxt.z = clampShift(nxt.z, N); nxt.w = clampShift(nxt.w, N);
            cur = nxt;
        }
    }

    // group sum over 4 lanes (each lane already holds 12 of the 48 e-values)
    ssum += __shfl_xor_sync(0xffffffffu, ssum, 1, 4);
    ssum += __shfl_xor_sync(0xffffffffu, ssum, 2, 4);
    if (gl == 0) invs[wIdx][p] = 1.0f / ssum;
    __syncwarp();

    // per-warp contiguous 1536B output: lane writes floats [lane*12, lane*12+12)
    {
        float* __restrict__ owarp = out + (size_t)warpId * 8 * K_NBR;
        const int pr = lane >> 2;                 // source pixel row
        const int kb = 12 * (lane & 3);           // base column
        const float iv = invs[wIdx][pr];
#pragma unroll
        for (int i = 0; i < 3; i++) {
            float4 v = *reinterpret_cast<const float4*>(
                &stage[wIdx][pr][kb + 4 * i]);
            v.x *= iv; v.y *= iv; v.z *= iv; v.w *= iv;
            *reinterpret_cast<float4*>(owarp + lane * 12 + 4 * i) = v;
        }
    }
}

// ---------------------------------------------------------------------------
extern "C" void kernel_launch(void* const* d_in, const int* in_sizes, int n_in,
                              void* d_out, int out_size) {
    const float* input1 = (const float*)d_in[0];   // [32, N] fp32
    const int*   input2 = (const int*)d_in[1];     // [N, 48] int32 (JAX x64 off)
    float*       out    = (float*)d_out;           // [N, 48] fp32

    const int N = in_sizes[0] / A_FEAT;   // 147456

    {
        dim3 blk(32, 8);
        dim3 grd(N / 32);
        transpose_kernel<<<grd, blk>>>(input1, N);
    }
    {
        const int threads = 256;
        const long long total = (long long)N * 4;   // 4 lanes per pixel
        const int blocks = (int)((total + threads - 1) / threads);
        dist_softmax_kernel<<<blocks, threads>>>(input2, out, N);
    }
}

// round 10
// speedup vs baseline: 2.4727x; 1.0108x over previous
#include <cuda_runtime.h>
#include <cuda_fp16.h>

#define N_MAX   (384*384)     // 147456 pixels
#define A_FEAT  32            // features per pixel
#define K_NBR   48            // neighbors per pixel
#define EPSV    1e-9f

// Row-major fp16 feature table UU[N][32] (64B rows, 128B-aligned base).
__device__ __align__(128) __half g_UUh[N_MAX * A_FEAT];

// ---------------------------------------------------------------------------
// Kernel 1: transpose + compress input1 [32, N] fp32 -> g_UUh [N, 32] fp16
// ---------------------------------------------------------------------------
__global__ void transpose_kernel(const float* __restrict__ in, int N) {
    __shared__ float tile[32][33];
    const int n0 = blockIdx.x * 32;
    const int tx = threadIdx.x;      // 0..31
    const int ty = threadIdx.y;      // 0..7
#pragma unroll
    for (int i = 0; i < 32; i += 8) {
        tile[ty + i][tx] = in[(size_t)(ty + i) * N + n0 + tx];
    }
    __syncthreads();
    __half2* __restrict__ out2 = reinterpret_cast<__half2*>(g_UUh);
    const int id = ty * 32 + tx;          // 0..255
    const int c  = id & 15;               // half2 column 0..15
    const int r0 = id >> 4;               // 0..15
#pragma unroll
    for (int rr = 0; rr < 2; rr++) {
        const int r = r0 + rr * 16;
        out2[(size_t)(n0 + r) * 16 + c] =
            __floats2half2_rn(tile[2 * c][r], tile[2 * c + 1][r]);
    }
}

__device__ __forceinline__ int clampShift(int v, int N) {
    return min(max(v, 0), N - 1) << 6;
}

// squared distance over this lane's 8 features (fp16x2, two depth-2 chains)
__device__ __forceinline__ float sqdist8(
        const uint4 r, const __half2 uh0, const __half2 uh1,
        const __half2 uh2, const __half2 uh3) {
    const __half2 vh0 = *reinterpret_cast<const __half2*>(&r.x);
    const __half2 vh1 = *reinterpret_cast<const __half2*>(&r.y);
    const __half2 vh2 = *reinterpret_cast<const __half2*>(&r.z);
    const __half2 vh3 = *reinterpret_cast<const __half2*>(&r.w);
    const __half2 d0 = __hsub2(uh0, vh0);
    const __half2 d1 = __hsub2(uh1, vh1);
    const __half2 d2 = __hsub2(uh2, vh2);
    const __half2 d3 = __hsub2(uh3, vh3);
    const __half2 qa = __hfma2(d1, d1, __hmul2(d0, d0));
    const __half2 qb = __hfma2(d3, d3, __hmul2(d2, d2));
    const __half2 q  = __hadd2(qa, qb);
    return __low2float(q) + __high2float(q);
}

// ---------------------------------------------------------------------------
// Kernel 2: 4 lanes per pixel (8 pixels/warp). Lane owns 16B (8 features).
// Gather: 4x LDG.128 per step (each covering 8 random rows = 8 lines, MLP=4).
// Offsets pre-clamped into padded smem; each step does ONE broadcast LDS.128
// instead of 4 shuffles. Softmax without max-subtraction (D<=0 always).
// ---------------------------------------------------------------------------
__global__ void __launch_bounds__(256, 6) dist_softmax_kernel(
        const int* __restrict__ idx,       // [N, 48] int32
        float* __restrict__ out, int N) {
    const int gtid   = blockIdx.x * blockDim.x + threadIdx.x;
    const int warpId = gtid >> 5;
    const int lane   = threadIdx.x & 31;
    const int p      = lane >> 2;        // pixel within warp 0..7
    const int gl     = lane & 3;         // lane within 4-lane group
    const int j      = warpId * 8 + p;   // pixel
    const int wIdx   = threadIdx.x >> 5; // warp within block
    if (j >= N) return;

    __shared__ int   offs[8][8][52];     // [warp][pixel][48 padded to 52]
    __shared__ float stage[8][8][52];
    __shared__ float invs[8][8];

    const char* __restrict__ gUU = reinterpret_cast<const char*>(g_UUh);
    const char* __restrict__ gUUlane = gUU + (gl << 4);   // lane's 16B slot

    // own 8 features as 4x half2
    __half2 uh0, uh1, uh2, uh3;
    {
        const uint4 uraw = *reinterpret_cast<const uint4*>(
            gUU + ((size_t)(unsigned)j << 6) + (gl << 4));
        uh0 = *reinterpret_cast<const __half2*>(&uraw.x);
        uh1 = *reinterpret_cast<const __half2*>(&uraw.y);
        uh2 = *reinterpret_cast<const __half2*>(&uraw.z);
        uh3 = *reinterpret_cast<const __half2*>(&uraw.w);
    }

    // preload + clamp all 48 offsets into smem (lane gl: int4 #(4q+gl),
    // covering neighbors 16q+4gl .. +3)
    {
        const int4* __restrict__ idx4 =
            reinterpret_cast<const int4*>(idx + (size_t)j * K_NBR);
#pragma unroll
        for (int q = 0; q < 3; q++) {
            int4 v = idx4[4 * q + gl];
            v.x = clampShift(v.x, N); v.y = clampShift(v.y, N);
            v.z = clampShift(v.z, N); v.w = clampShift(v.w, N);
            *reinterpret_cast<int4*>(&offs[wIdx][p][16 * q + 4 * gl]) = v;
        }
    }
    __syncwarp();

    const bool b0 = (gl & 1) != 0;
    const bool b1 = (gl & 2) != 0;

    float ssum = 0.0f;
#pragma unroll
    for (int t = 0; t < 12; t++) {
        // one broadcast LDS.128: the 4 offsets of this step (all group lanes
        // read the same 16B; pixels hit distinct banks via 52-word padding)
        const int4 o = *reinterpret_cast<const int4*>(&offs[wIdx][p][4 * t]);
        const uint4 r0 = *reinterpret_cast<const uint4*>(gUUlane + (size_t)(unsigned)o.x);
        const uint4 r1 = *reinterpret_cast<const uint4*>(gUUlane + (size_t)(unsigned)o.y);
        const uint4 r2 = *reinterpret_cast<const uint4*>(gUUlane + (size_t)(unsigned)o.z);
        const uint4 r3 = *reinterpret_cast<const uint4*>(gUUlane + (size_t)(unsigned)o.w);

        const float a0 = sqdist8(r0, uh0, uh1, uh2, uh3);
        const float a1 = sqdist8(r1, uh0, uh1, uh2, uh3);
        const float a2 = sqdist8(r2, uh0, uh1, uh2, uh3);
        const float a3 = sqdist8(r3, uh0, uh1, uh2, uh3);

        // 3-shfl multi-value butterfly (width 4): lane gl keeps s = gl
        const float u0 = b0 ? a1 : a0;
        const float s0 = b0 ? a0 : a1;
        const float u1 = b0 ? a3 : a2;
        const float s1 = b0 ? a2 : a3;
        const float m0 = u0 + __shfl_xor_sync(0xffffffffu, s0, 1, 4);
        const float m1 = u1 + __shfl_xor_sync(0xffffffffu, s1, 1, 4);
        const float uu = b1 ? m1 : m0;
        const float sv = b1 ? m0 : m1;
        const float Dt = uu + __shfl_xor_sync(0xffffffffu, sv, 2, 4);

        // e = exp(-sqrt(mean+eps))  (no max-sub: arg is in (-10, 0])
        const float e = __expf(-sqrtf(fmaf(Dt, 1.0f / 32.0f, EPSV)));
        ssum += e;
        stage[wIdx][p][4 * t + gl] = e;     // neighbor 4t+gl
    }

    // group sum over 4 lanes
    ssum += __shfl_xor_sync(0xffffffffu, ssum, 1, 4);
    ssum += __shfl_xor_sync(0xffffffffu, ssum, 2, 4);
    if (gl == 0) invs[wIdx][p] = 1.0f / ssum;
    __syncwarp();

    // per-warp contiguous 1536B output: lane writes floats [lane*12, lane*12+12)
    {
        float* __restrict__ owarp = out + (size_t)warpId * 8 * K_NBR;
        const int pr = lane >> 2;                 // source pixel row
        const int kb = 12 * (lane & 3);           // base column
        const float iv = invs[wIdx][pr];
#pragma unroll
        for (int i = 0; i < 3; i++) {
            float4 v = *reinterpret_cast<const float4*>(
                &stage[wIdx][pr][kb + 4 * i]);
            v.x *= iv; v.y *= iv; v.z *= iv; v.w *= iv;
            *reinterpret_cast<float4*>(owarp + lane * 12 + 4 * i) = v;
        }
    }
}

// ---------------------------------------------------------------------------
extern "C" void kernel_launch(void* const* d_in, const int* in_sizes, int n_in,
                              void* d_out, int out_size) {
    const float* input1 = (const float*)d_in[0];   // [32, N] fp32
    const int*   input2 = (const int*)d_in[1];     // [N, 48] int32 (JAX x64 off)
    float*       out    = (float*)d_out;           // [N, 48] fp32

    const int N = in_sizes[0] / A_FEAT;   // 147456

    {
        dim3 blk(32, 8);
        dim3 grd(N / 32);
        transpose_kernel<<<grd, blk>>>(input1, N);
    }
    {
        const int threads = 256;
        const long long total = (long long)N * 4;   // 4 lanes per pixel
        const int blocks = (int)((total + threads - 1) / threads);
        dist_softmax_kernel<<<blocks, threads>>>(input2, out, N);
    }
}